// round 3
// baseline (speedup 1.0000x reference)
#include <cuda_runtime.h>

#define NPTS  2048
#define BATCH 8
#define CINCH 64
#define COUTC 128
#define KNNK  16

// d_out partitioning (float elements)
constexpr size_t OUT2_OFF = (size_t)BATCH * COUTC * NPTS;                     // 2,097,152
constexpr size_t LC_OFF   = OUT2_OFF + (size_t)BATCH * COUTC * NPTS * KNNK;   // 35,651,584

// scratch (no allocations allowed -> device globals)
__device__ float g_sq[BATCH * NPTS];
__device__ int   g_idx[BATCH * NPTS * KNNK];

// ---------- packed fp32x2 helpers ----------
__device__ __forceinline__ unsigned long long pack2(float a, float b) {
    unsigned long long r;
    asm("mov.b64 %0, {%1, %2};" : "=l"(r) : "f"(a), "f"(b));
    return r;
}
__device__ __forceinline__ void unpack2(unsigned long long v, float& a, float& b) {
    asm("mov.b64 {%0, %1}, %2;" : "=f"(a), "=f"(b) : "l"(v));
}
__device__ __forceinline__ void ffma2(unsigned long long& d, unsigned long long a,
                                      unsigned long long b) {
    asm("fma.rn.f32x2 %0, %1, %2, %0;" : "+l"(d) : "l"(a), "l"(b));
}
__device__ __forceinline__ unsigned long long umin64(unsigned long long a,
                                                     unsigned long long b) {
    return a < b ? a : b;
}

// ---------- kernel 1: squared norms (exact replication of reference rounding) ----------
__global__ void sq_kernel(const float* __restrict__ coords) {
    int i = blockIdx.x * blockDim.x + threadIdx.x;  // 0..16383
    int b = i >> 11, n = i & (NPTS - 1);
    const float* cb = coords + (size_t)b * 3 * NPTS;
    float x = cb[n], y = cb[NPTS + n], z = cb[2 * NPTS + n];
    float xx = __fmul_rn(x, x);
    float yy = __fmul_rn(y, y);
    float zz = __fmul_rn(z, z);
    g_sq[i] = __fadd_rn(__fadd_rn(xx, yy), zz);
}

// ---------- kernel 2: KNN (top-16 ascending d2, tie -> smaller index) + local coords ----
// 256 threads per query. Keys strictly in registers (no dynamic indexing -> no local mem).
// Phase 1: each warp extracts its exact top-16 of its 256 candidates (shfl allreduce
// argmin, no block barriers). Phase 2: warp 0 merges the 8x16 survivors.
__global__ void __launch_bounds__(256) knn_kernel(const float* __restrict__ coords,
                                                  float* __restrict__ dout) {
    const int bn = blockIdx.x;                 // 0..16383
    const int b = bn >> 11, n = bn & (NPTS - 1);
    const int tid = threadIdx.x;               // 256 threads
    const int w = tid >> 5, lane = tid & 31;
    const float* cb = coords + (size_t)b * 3 * NPTS;
    const float qx = cb[n], qy = cb[NPTS + n], qz = cb[2 * NPTS + n];
    const float sqn = g_sq[bn];

    unsigned long long keys[8];
#pragma unroll
    for (int i = 0; i < 8; ++i) {
        int m = tid + (i << 8);
        float mx = cb[m], my = cb[NPTS + m], mz = cb[2 * NPTS + m];
        // reference dot: sgemm K=3 fma chain, k ascending, acc starts at 0
        float dot = fmaf(qz, mz, fmaf(qy, my, __fmul_rn(qx, mx)));
        // reference d2: (sq_n + sq_m) - (2*dot), separate rounded ops, no fma
        float t  = __fadd_rn(sqn, g_sq[(b << 11) + m]);
        float d2 = __fsub_rn(t, __fmul_rn(2.0f, dot));
        unsigned u = __float_as_uint(d2);
        u = (u & 0x80000000u) ? ~u : (u | 0x80000000u);   // sortable float bits
        keys[i] = ((unsigned long long)u << 32) | (unsigned)m;
    }

    __shared__ unsigned long long list[8 * KNNK];   // per-warp top-16 lists
    __shared__ int sel[KNNK];

    // ---- phase 1: warp-local exact top-16 (registers only) ----
    unsigned long long wtop = ~0ull;
#pragma unroll
    for (int r = 0; r < KNNK; ++r) {
        unsigned long long best =
            umin64(umin64(umin64(keys[0], keys[1]), umin64(keys[2], keys[3])),
                   umin64(umin64(keys[4], keys[5]), umin64(keys[6], keys[7])));
#pragma unroll
        for (int off = 16; off; off >>= 1)
            best = umin64(best, __shfl_xor_sync(0xffffffffu, best, off));
        if (lane == r) wtop = best;
#pragma unroll
        for (int i = 0; i < 8; ++i)
            keys[i] = (keys[i] == best) ? ~0ull : keys[i];
    }
    if (lane < KNNK) list[w * KNNK + lane] = wtop;
    __syncthreads();

    // ---- phase 2: warp 0 merges 128 survivors ----
    if (w == 0) {
        unsigned long long k2[4];
#pragma unroll
        for (int q = 0; q < 4; ++q) k2[q] = list[lane * 4 + q];
#pragma unroll
        for (int r = 0; r < KNNK; ++r) {
            unsigned long long best =
                umin64(umin64(k2[0], k2[1]), umin64(k2[2], k2[3]));
#pragma unroll
            for (int off = 16; off; off >>= 1)
                best = umin64(best, __shfl_xor_sync(0xffffffffu, best, off));
            if (lane == 0) sel[r] = (int)(best & 0xffffffffull);
#pragma unroll
            for (int q = 0; q < 4; ++q)
                k2[q] = (k2[q] == best) ? ~0ull : k2[q];
        }
    }
    __syncthreads();

    if (tid < KNNK) g_idx[bn * KNNK + tid] = sel[tid];
    if (tid < 3 * KNNK) {
        int c = tid >> 4, k = tid & 15;
        float center = cb[c * NPTS + n];
        float nb = cb[c * NPTS + sel[k]];
        dout[LC_OFF + (((size_t)(b * 3 + c) * NPTS) + n) * KNNK + k] = __fsub_rn(center, nb);
    }
}

// ---------- kernel 3: fused gather -> conv1+BN+ReLU -> conv2+BN+ReLU -> max_k ----------
__global__ void __launch_bounds__(256, 1) mlp_kernel(
    const float* __restrict__ x,
    const float* __restrict__ w1, const float* __restrict__ w2,
    const float* __restrict__ g1, const float* __restrict__ b1,
    const float* __restrict__ m1, const float* __restrict__ v1,
    const float* __restrict__ g2, const float* __restrict__ b2,
    const float* __restrict__ m2, const float* __restrict__ v2,
    float* __restrict__ dout) {
    extern __shared__ float smem[];
    float* ws1 = smem;                        // [64][128]  ws1[c*128+o] = w1[o][c]
    float* ws2 = ws1 + CINCH * COUTC;         // [128][128] ws2[c*128+o] = w2[o][c]
    float* xsAll = ws2 + COUTC * COUTC;       // 8 * 1024 floats
    unsigned long long* hsAll =
        (unsigned long long*)(xsAll + 8 * CINCH * KNNK);  // 8 * 1024 u64

    const int tid = threadIdx.x;
    const int w = tid >> 5, lane = tid & 31;

    for (int i = tid; i < CINCH * COUTC; i += 256) {
        int c = i >> 7, o = i & 127;
        ws1[i] = w1[o * CINCH + c];
    }
    for (int i = tid; i < COUTC * COUTC; i += 256) {
        int c = i >> 7, o = i & 127;
        ws2[i] = w2[o * COUTC + c];
    }

    // BN constants for this thread's 4 channels (o = j*32 + lane)
    float s1v[4], c1v[4], s2v[4], c2v[4];
#pragma unroll
    for (int j = 0; j < 4; ++j) {
        int ch = j * 32 + lane;
        float s1 = g1[ch] / sqrtf(v1[ch] + 1e-5f);
        s1v[j] = s1; c1v[j] = b1[ch] - m1[ch] * s1;
        float s2 = g2[ch] / sqrtf(v2[ch] + 1e-5f);
        s2v[j] = s2; c2v[j] = b2[ch] - m2[ch] * s2;
    }
    __syncthreads();

    const int p = blockIdx.x * 8 + w;           // point id 0..16383
    const int b = p >> 11, n = p & (NPTS - 1);
    float* xs = xsAll + w * (CINCH * KNNK);
    unsigned long long* hs = hsAll + w * (COUTC * KNNK / 2);

    // gather neighbors: xs[c*16 + k] = x[b][c][idx[k]]
    {
        const int k = lane & 15;
        const int id = __ldg(&g_idx[p * KNNK + k]);
        const float* xb = x + (size_t)b * CINCH * NPTS;
        for (int c = (lane >> 4); c < CINCH; c += 2)
            xs[c * KNNK + k] = __ldg(&xb[c * NPTS + id]);
    }
    __syncwarp();

    unsigned long long acc[4][8];
#pragma unroll
    for (int j = 0; j < 4; ++j)
#pragma unroll
        for (int q = 0; q < 8; ++q) acc[j][q] = 0ull;

    // GEMM1: h[o][k] = sum_c w1[o][c] * xs[c][k]
    const ulonglong2* xs2 = (const ulonglong2*)xs;
#pragma unroll 4
    for (int c = 0; c < CINCH; ++c) {
        ulonglong2 xv0 = xs2[c * 4 + 0];
        ulonglong2 xv1 = xs2[c * 4 + 1];
        ulonglong2 xv2 = xs2[c * 4 + 2];
        ulonglong2 xv3 = xs2[c * 4 + 3];
        const float* wr = ws1 + c * COUTC + lane;
#pragma unroll
        for (int j = 0; j < 4; ++j) {
            float wv = wr[j * 32];
            unsigned long long wp = pack2(wv, wv);
            ffma2(acc[j][0], wp, xv0.x);
            ffma2(acc[j][1], wp, xv0.y);
            ffma2(acc[j][2], wp, xv1.x);
            ffma2(acc[j][3], wp, xv1.y);
            ffma2(acc[j][4], wp, xv2.x);
            ffma2(acc[j][5], wp, xv2.y);
            ffma2(acc[j][6], wp, xv3.x);
            ffma2(acc[j][7], wp, xv3.y);
        }
    }

    // epilogue 1: BN+ReLU, store h packed as hs[q*128 + ch] (k = 2q, 2q+1)
#pragma unroll
    for (int j = 0; j < 4; ++j) {
        int ch = j * 32 + lane;
#pragma unroll
        for (int q = 0; q < 8; ++q) {
            float lo, hi; unpack2(acc[j][q], lo, hi);
            lo = fmaxf(fmaf(lo, s1v[j], c1v[j]), 0.f);
            hi = fmaxf(fmaf(hi, s1v[j], c1v[j]), 0.f);
            hs[q * COUTC + ch] = pack2(lo, hi);
        }
    }
    __syncwarp();

#pragma unroll
    for (int j = 0; j < 4; ++j)
#pragma unroll
        for (int q = 0; q < 8; ++q) acc[j][q] = 0ull;

    // GEMM2: out[o][k] = sum_c w2[o][c] * h[c][k]
#pragma unroll 4
    for (int c = 0; c < COUTC; ++c) {
        unsigned long long hv[8];
#pragma unroll
        for (int q = 0; q < 8; ++q) hv[q] = hs[q * COUTC + c];
        const float* wr = ws2 + c * COUTC + lane;
#pragma unroll
        for (int j = 0; j < 4; ++j) {
            float wv = wr[j * 32];
            unsigned long long wp = pack2(wv, wv);
#pragma unroll
            for (int q = 0; q < 8; ++q) ffma2(acc[j][q], wp, hv[q]);
        }
    }

    // epilogue 2: BN+ReLU, write knn_mlp_x and y (max over k; ReLU => max >= 0)
    float* out2 = dout + OUT2_OFF;
#pragma unroll
    for (int j = 0; j < 4; ++j) {
        int ch = j * 32 + lane;
        float vals[16];
        float mx = 0.f;
#pragma unroll
        for (int q = 0; q < 8; ++q) {
            float lo, hi; unpack2(acc[j][q], lo, hi);
            lo = fmaxf(fmaf(lo, s2v[j], c2v[j]), 0.f);
            hi = fmaxf(fmaf(hi, s2v[j], c2v[j]), 0.f);
            mx = fmaxf(mx, fmaxf(lo, hi));
            vals[2 * q] = lo; vals[2 * q + 1] = hi;
        }
        float4* o4 = (float4*)(out2 + (((size_t)(b * COUTC + ch)) * NPTS + n) * KNNK);
        o4[0] = make_float4(vals[0], vals[1], vals[2], vals[3]);
        o4[1] = make_float4(vals[4], vals[5], vals[6], vals[7]);
        o4[2] = make_float4(vals[8], vals[9], vals[10], vals[11]);
        o4[3] = make_float4(vals[12], vals[13], vals[14], vals[15]);
        dout[(size_t)(b * COUTC + ch) * NPTS + n] = mx;
    }
}

extern "C" void kernel_launch(void* const* d_in, const int* in_sizes, int n_in,
                              void* d_out, int out_size) {
    const float* x      = (const float*)d_in[0];
    const float* coords = (const float*)d_in[1];
    const float* w1     = (const float*)d_in[2];
    const float* g1     = (const float*)d_in[3];
    const float* b1     = (const float*)d_in[4];
    const float* m1     = (const float*)d_in[5];
    const float* v1     = (const float*)d_in[6];
    const float* w2     = (const float*)d_in[7];
    const float* g2     = (const float*)d_in[8];
    const float* b2     = (const float*)d_in[9];
    const float* m2     = (const float*)d_in[10];
    const float* v2     = (const float*)d_in[11];
    float* out = (float*)d_out;

    sq_kernel<<<(BATCH * NPTS) / 256, 256>>>(coords);
    knn_kernel<<<BATCH * NPTS, 256>>>(coords, out);

    const int smem_bytes = (CINCH * COUTC + COUTC * COUTC + 8 * CINCH * KNNK) * 4
                         + 8 * (COUTC * KNNK / 2) * 8;   // 196608 = 192 KB
    cudaFuncSetAttribute(mlp_kernel, cudaFuncAttributeMaxDynamicSharedMemorySize, smem_bytes);
    mlp_kernel<<<(BATCH * NPTS) / 8, 256, smem_bytes>>>(
        x, w1, w2, g1, b1, m1, v1, g2, b2, m2, v2, out);
}

// round 4
// speedup vs baseline: 1.8668x; 1.8668x over previous
#include <cuda_runtime.h>

#define NPTS  2048
#define BATCH 8
#define CINCH 64
#define COUTC 128
#define KNNK  16

// d_out partitioning (float elements)
constexpr size_t OUT2_OFF = (size_t)BATCH * COUTC * NPTS;                     // 2,097,152
constexpr size_t LC_OFF   = OUT2_OFF + (size_t)BATCH * COUTC * NPTS * KNNK;   // 35,651,584

// scratch (no allocations allowed -> device globals)
__device__ int g_idx[BATCH * NPTS * KNNK];

// ---------- packed fp32x2 helpers ----------
__device__ __forceinline__ unsigned long long pack2(float a, float b) {
    unsigned long long r;
    asm("mov.b64 %0, {%1, %2};" : "=l"(r) : "f"(a), "f"(b));
    return r;
}
__device__ __forceinline__ void unpack2(unsigned long long v, float& a, float& b) {
    asm("mov.b64 {%0, %1}, %2;" : "=f"(a), "=f"(b) : "l"(v));
}
__device__ __forceinline__ void ffma2(unsigned long long& d, unsigned long long a,
                                      unsigned long long b) {
    asm("fma.rn.f32x2 %0, %1, %2, %0;" : "+l"(d) : "l"(a), "l"(b));
}
__device__ __forceinline__ unsigned long long umin64(unsigned long long a,
                                                     unsigned long long b) {
    return a < b ? a : b;
}

// ---------- kernel 1: KNN (top-16 ascending d2, tie -> smaller index) + local coords ----
// sq-norms fused (bit-identical rounding to the reference's separate square+sum).
// Keys strictly in registers; per-thread min maintained incrementally; winner
// invalidated by 64-bit equality compare (keys are unique: index in low bits).
__global__ void __launch_bounds__(256) knn_kernel(const float* __restrict__ coords,
                                                  float* __restrict__ dout) {
    const int bn = blockIdx.x;                 // 0..16383
    const int b = bn >> 11, n = bn & (NPTS - 1);
    const int tid = threadIdx.x;               // 256 threads
    const int w = tid >> 5, lane = tid & 31;
    const float* cb = coords + (size_t)b * 3 * NPTS;
    const float qx = cb[n], qy = cb[NPTS + n], qz = cb[2 * NPTS + n];
    // reference sq: rounded squares then sequential adds, no fma
    const float sqn = __fadd_rn(__fadd_rn(__fmul_rn(qx, qx), __fmul_rn(qy, qy)),
                                __fmul_rn(qz, qz));

    unsigned long long keys[8];
#pragma unroll
    for (int i = 0; i < 8; ++i) {
        int m = tid + (i << 8);
        float mx = cb[m], my = cb[NPTS + m], mz = cb[2 * NPTS + m];
        float sqm = __fadd_rn(__fadd_rn(__fmul_rn(mx, mx), __fmul_rn(my, my)),
                              __fmul_rn(mz, mz));
        // reference dot: sgemm K=3 fma chain, k ascending, acc starts at 0
        float dot = fmaf(qz, mz, fmaf(qy, my, __fmul_rn(qx, mx)));
        // reference d2: (sq_n + sq_m) - (2*dot), separate rounded ops, no fma
        float t  = __fadd_rn(sqn, sqm);
        float d2 = __fsub_rn(t, __fmul_rn(2.0f, dot));
        unsigned u = __float_as_uint(d2);
        u = (u & 0x80000000u) ? ~u : (u | 0x80000000u);   // sortable float bits
        keys[i] = ((unsigned long long)u << 32) | (unsigned)m;
    }

    // per-thread min (tournament once; maintained incrementally afterwards)
    unsigned long long tmin =
        umin64(umin64(umin64(keys[0], keys[1]), umin64(keys[2], keys[3])),
               umin64(umin64(keys[4], keys[5]), umin64(keys[6], keys[7])));

    __shared__ unsigned long long wmin[8];
    __shared__ unsigned long long wsel[KNNK];

    for (int r = 0; r < KNNK; ++r) {
        unsigned long long v = tmin;
#pragma unroll
        for (int off = 16; off; off >>= 1)
            v = umin64(v, __shfl_xor_sync(0xffffffffu, v, off));
        if (lane == 0) wmin[w] = v;
        __syncthreads();
        if (tid == 0) {
            unsigned long long bb = wmin[0];
#pragma unroll
            for (int wi = 1; wi < 8; ++wi) bb = umin64(bb, wmin[wi]);
            wsel[r] = bb;
        }
        __syncthreads();
        unsigned long long kk = wsel[r];
        if (tmin == kk) {                     // exactly one owner thread per block
#pragma unroll
            for (int i = 0; i < 8; ++i)
                keys[i] = (keys[i] == kk) ? ~0ull : keys[i];
            tmin = umin64(umin64(umin64(keys[0], keys[1]), umin64(keys[2], keys[3])),
                          umin64(umin64(keys[4], keys[5]), umin64(keys[6], keys[7])));
        }
    }

    if (tid < KNNK) g_idx[bn * KNNK + tid] = (int)(wsel[tid] & 0xffffffffull);
    if (tid < 3 * KNNK) {
        int c = tid >> 4, k = tid & 15;
        int id = (int)(wsel[k] & 0xffffffffull);
        float center = cb[c * NPTS + n];
        float nb = cb[c * NPTS + id];
        dout[LC_OFF + (((size_t)(b * 3 + c) * NPTS) + n) * KNNK + k] = __fsub_rn(center, nb);
    }
}

// ---------- kernel 2: fused gather -> conv1+BN+ReLU -> conv2+BN+ReLU -> max_k ----------
// 512 threads = 16 warps; 8 points per block, 2 warps per point (64 out-ch each).
__global__ void __launch_bounds__(512, 1) mlp_kernel(
    const float* __restrict__ x,
    const float* __restrict__ w1, const float* __restrict__ w2,
    const float* __restrict__ g1, const float* __restrict__ b1,
    const float* __restrict__ m1, const float* __restrict__ v1,
    const float* __restrict__ g2, const float* __restrict__ b2,
    const float* __restrict__ m2, const float* __restrict__ v2,
    float* __restrict__ dout) {
    extern __shared__ float smem[];
    float* ws1 = smem;                        // [64][128]  ws1[c*128+o] = w1[o][c]
    float* ws2 = ws1 + CINCH * COUTC;         // [128][128] ws2[c*128+o] = w2[o][c]
    float* xsAll = ws2 + COUTC * COUTC;       // 8 * 1024 floats
    unsigned long long* hsAll =
        (unsigned long long*)(xsAll + 8 * CINCH * KNNK);  // 8 * 1024 u64

    const int tid = threadIdx.x;
    const int wid = tid >> 5, lane = tid & 31;
    const int pp = wid >> 1;                  // point within block (0..7)
    const int half = wid & 1;                 // out-channel half (0..1)

    for (int i = tid; i < CINCH * COUTC; i += 512) {
        int c = i >> 7, o = i & 127;
        ws1[i] = w1[o * CINCH + c];
    }
    for (int i = tid; i < COUTC * COUTC; i += 512) {
        int c = i >> 7, o = i & 127;
        ws2[i] = w2[o * COUTC + c];
    }

    // BN constants for this thread's 2 channels (ch = half*64 + j*32 + lane)
    float s1v[2], c1v[2], s2v[2], c2v[2];
#pragma unroll
    for (int j = 0; j < 2; ++j) {
        int ch = half * 64 + j * 32 + lane;
        float s1 = g1[ch] / sqrtf(v1[ch] + 1e-5f);
        s1v[j] = s1; c1v[j] = b1[ch] - m1[ch] * s1;
        float s2 = g2[ch] / sqrtf(v2[ch] + 1e-5f);
        s2v[j] = s2; c2v[j] = b2[ch] - m2[ch] * s2;
    }

    const int p = blockIdx.x * 8 + pp;          // point id 0..16383
    const int b = p >> 11, n = p & (NPTS - 1);
    float* xs = xsAll + pp * (CINCH * KNNK);
    unsigned long long* hs = hsAll + pp * (COUTC * KNNK / 2);

    __syncthreads();

    // gather neighbors (64 threads per point): xs[c*16 + k] = x[b][c][idx[k]]
    {
        const int t2 = tid & 63;
        const int k = t2 & 15;
        const int c0 = t2 >> 4;                 // 0..3
        const int id = __ldg(&g_idx[p * KNNK + k]);
        const float* xb = x + (size_t)b * CINCH * NPTS;
#pragma unroll
        for (int c = c0; c < CINCH; c += 4)
            xs[c * KNNK + k] = __ldg(&xb[c * NPTS + id]);
    }
    __syncthreads();

    unsigned long long acc[2][8];
#pragma unroll
    for (int j = 0; j < 2; ++j)
#pragma unroll
        for (int q = 0; q < 8; ++q) acc[j][q] = 0ull;

    // GEMM1: h[o][k] = sum_c w1[o][c] * xs[c][k]
    const ulonglong2* xs2 = (const ulonglong2*)xs;
#pragma unroll 4
    for (int c = 0; c < CINCH; ++c) {
        ulonglong2 xv0 = xs2[c * 4 + 0];
        ulonglong2 xv1 = xs2[c * 4 + 1];
        ulonglong2 xv2 = xs2[c * 4 + 2];
        ulonglong2 xv3 = xs2[c * 4 + 3];
        const float* wr = ws1 + c * COUTC + half * 64 + lane;
#pragma unroll
        for (int j = 0; j < 2; ++j) {
            float wv = wr[j * 32];
            unsigned long long wp = pack2(wv, wv);
            ffma2(acc[j][0], wp, xv0.x);
            ffma2(acc[j][1], wp, xv0.y);
            ffma2(acc[j][2], wp, xv1.x);
            ffma2(acc[j][3], wp, xv1.y);
            ffma2(acc[j][4], wp, xv2.x);
            ffma2(acc[j][5], wp, xv2.y);
            ffma2(acc[j][6], wp, xv3.x);
            ffma2(acc[j][7], wp, xv3.y);
        }
    }

    // epilogue 1: BN+ReLU, store h packed as hs[q*128 + ch] (k = 2q, 2q+1)
#pragma unroll
    for (int j = 0; j < 2; ++j) {
        int ch = half * 64 + j * 32 + lane;
#pragma unroll
        for (int q = 0; q < 8; ++q) {
            float lo, hi; unpack2(acc[j][q], lo, hi);
            lo = fmaxf(fmaf(lo, s1v[j], c1v[j]), 0.f);
            hi = fmaxf(fmaf(hi, s1v[j], c1v[j]), 0.f);
            hs[q * COUTC + ch] = pack2(lo, hi);
        }
    }
    __syncthreads();   // warp pair must see both halves of h

#pragma unroll
    for (int j = 0; j < 2; ++j)
#pragma unroll
        for (int q = 0; q < 8; ++q) acc[j][q] = 0ull;

    // GEMM2: out[o][k] = sum_c w2[o][c] * h[c][k]  (h loads vectorized 2 c at a time)
    const ulonglong2* hs2 = (const ulonglong2*)hs;
#pragma unroll 2
    for (int c2 = 0; c2 < COUTC / 2; ++c2) {
        ulonglong2 hp[8];
#pragma unroll
        for (int q = 0; q < 8; ++q) hp[q] = hs2[q * (COUTC / 2) + c2];
        const float* wr0 = ws2 + (2 * c2) * COUTC + half * 64 + lane;
#pragma unroll
        for (int j = 0; j < 2; ++j) {
            float wa = wr0[j * 32];
            float wb = wr0[COUTC + j * 32];
            unsigned long long wpa = pack2(wa, wa);
            unsigned long long wpb = pack2(wb, wb);
#pragma unroll
            for (int q = 0; q < 8; ++q) {
                ffma2(acc[j][q], wpa, hp[q].x);
                ffma2(acc[j][q], wpb, hp[q].y);
            }
        }
    }

    // epilogue 2: BN+ReLU, write knn_mlp_x and y (max over k; ReLU => max >= 0)
    float* out2 = dout + OUT2_OFF;
#pragma unroll
    for (int j = 0; j < 2; ++j) {
        int ch = half * 64 + j * 32 + lane;
        float4* o4 = (float4*)(out2 + (((size_t)(b * COUTC + ch)) * NPTS + n) * KNNK);
        float mx = 0.f;
#pragma unroll
        for (int q4 = 0; q4 < 4; ++q4) {
            float a0, a1, a2, a3;
            unpack2(acc[j][2 * q4], a0, a1);
            unpack2(acc[j][2 * q4 + 1], a2, a3);
            a0 = fmaxf(fmaf(a0, s2v[j], c2v[j]), 0.f);
            a1 = fmaxf(fmaf(a1, s2v[j], c2v[j]), 0.f);
            a2 = fmaxf(fmaf(a2, s2v[j], c2v[j]), 0.f);
            a3 = fmaxf(fmaf(a3, s2v[j], c2v[j]), 0.f);
            mx = fmaxf(mx, fmaxf(fmaxf(a0, a1), fmaxf(a2, a3)));
            o4[q4] = make_float4(a0, a1, a2, a3);
        }
        dout[(size_t)(b * COUTC + ch) * NPTS + n] = mx;
    }
}

extern "C" void kernel_launch(void* const* d_in, const int* in_sizes, int n_in,
                              void* d_out, int out_size) {
    const float* x      = (const float*)d_in[0];
    const float* coords = (const float*)d_in[1];
    const float* w1     = (const float*)d_in[2];
    const float* g1     = (const float*)d_in[3];
    const float* b1     = (const float*)d_in[4];
    const float* m1     = (const float*)d_in[5];
    const float* v1     = (const float*)d_in[6];
    const float* w2     = (const float*)d_in[7];
    const float* g2     = (const float*)d_in[8];
    const float* b2     = (const float*)d_in[9];
    const float* m2     = (const float*)d_in[10];
    const float* v2     = (const float*)d_in[11];
    float* out = (float*)d_out;

    knn_kernel<<<BATCH * NPTS, 256>>>(coords, out);

    const int smem_bytes = (CINCH * COUTC + COUTC * COUTC + 8 * CINCH * KNNK) * 4
                         + 8 * (COUTC * KNNK / 2) * 8;   // 196608 = 192 KB
    cudaFuncSetAttribute(mlp_kernel, cudaFuncAttributeMaxDynamicSharedMemorySize, smem_bytes);
    mlp_kernel<<<(BATCH * NPTS) / 8, 512, smem_bytes>>>(
        x, w1, w2, g1, b1, m1, v1, g2, b2, m2, v2, out);
}

// round 5
// speedup vs baseline: 1.9524x; 1.0458x over previous
#include <cuda_runtime.h>

#define NPTS  2048
#define BATCH 8
#define CINCH 64
#define COUTC 128
#define KNNK  16

// d_out partitioning (float elements)
constexpr size_t OUT2_OFF = (size_t)BATCH * COUTC * NPTS;                     // 2,097,152
constexpr size_t LC_OFF   = OUT2_OFF + (size_t)BATCH * COUTC * NPTS * KNNK;   // 35,651,584

// scratch (no allocations allowed -> device globals)
__device__ int   g_idx[BATCH * NPTS * KNNK];
__device__ float g_xt[BATCH * NPTS * CINCH];   // x transposed to [b][n][c], 4MB

// activation SMEM swizzle (u64 granularity): slot for (c, kq)
#define SWZ(c, kq) ((c) * 8 + ((kq) ^ (((c) >> 2) & 7)))

// ---------- packed fp32x2 helpers ----------
__device__ __forceinline__ unsigned long long pack2(float a, float b) {
    unsigned long long r;
    asm("mov.b64 %0, {%1, %2};" : "=l"(r) : "f"(a), "f"(b));
    return r;
}
__device__ __forceinline__ void unpack2(unsigned long long v, float& a, float& b) {
    asm("mov.b64 {%0, %1}, %2;" : "=f"(a), "=f"(b) : "l"(v));
}
__device__ __forceinline__ void ffma2(unsigned long long& d, unsigned long long a,
                                      unsigned long long b) {
    asm("fma.rn.f32x2 %0, %1, %2, %0;" : "+l"(d) : "l"(a), "l"(b));
}
__device__ __forceinline__ unsigned long long umin64(unsigned long long a,
                                                     unsigned long long b) {
    return a < b ? a : b;
}

// ---------- kernel 0: transpose x[b][c][n] -> g_xt[b][n][c] ----------
__global__ void __launch_bounds__(256) transpose_kernel(const float* __restrict__ x) {
    __shared__ float t[64][65];
    const int b = blockIdx.y, n0 = blockIdx.x * 64;
    const int tid = threadIdx.x;
    const int nn = tid & 63, cq = tid >> 6;          // cq 0..3
#pragma unroll
    for (int i = 0; i < 16; ++i) {
        int c = i * 4 + cq;
        t[c][nn] = x[((size_t)b * CINCH + c) * NPTS + n0 + nn];
    }
    __syncthreads();
    const int nr = tid >> 2, q = tid & 3;            // nr 0..63
    float4* dst = (float4*)(g_xt + ((size_t)b * NPTS + n0 + nr) * CINCH);
#pragma unroll
    for (int i = 0; i < 4; ++i) {
        int c4 = i * 4 + q;                          // 0..15
        dst[c4] = make_float4(t[c4 * 4 + 0][nr], t[c4 * 4 + 1][nr],
                              t[c4 * 4 + 2][nr], t[c4 * 4 + 3][nr]);
    }
}

// ---------- kernel 1: KNN (top-16 ascending d2, tie -> smaller index) + local coords ----
__global__ void __launch_bounds__(256) knn_kernel(const float* __restrict__ coords,
                                                  float* __restrict__ dout) {
    const int bn = blockIdx.x;                 // 0..16383
    const int b = bn >> 11, n = bn & (NPTS - 1);
    const int tid = threadIdx.x;               // 256 threads
    const int w = tid >> 5, lane = tid & 31;
    const float* cb = coords + (size_t)b * 3 * NPTS;
    const float qx = cb[n], qy = cb[NPTS + n], qz = cb[2 * NPTS + n];
    const float sqn = __fadd_rn(__fadd_rn(__fmul_rn(qx, qx), __fmul_rn(qy, qy)),
                                __fmul_rn(qz, qz));

    unsigned long long keys[8];
#pragma unroll
    for (int i = 0; i < 8; ++i) {
        int m = tid + (i << 8);
        float mx = cb[m], my = cb[NPTS + m], mz = cb[2 * NPTS + m];
        float sqm = __fadd_rn(__fadd_rn(__fmul_rn(mx, mx), __fmul_rn(my, my)),
                              __fmul_rn(mz, mz));
        float dot = fmaf(qz, mz, fmaf(qy, my, __fmul_rn(qx, mx)));
        float t  = __fadd_rn(sqn, sqm);
        float d2 = __fsub_rn(t, __fmul_rn(2.0f, dot));
        unsigned u = __float_as_uint(d2);
        u = (u & 0x80000000u) ? ~u : (u | 0x80000000u);   // sortable float bits
        keys[i] = ((unsigned long long)u << 32) | (unsigned)m;
    }

    unsigned long long tmin =
        umin64(umin64(umin64(keys[0], keys[1]), umin64(keys[2], keys[3])),
               umin64(umin64(keys[4], keys[5]), umin64(keys[6], keys[7])));

    __shared__ unsigned long long wmin[8];
    __shared__ unsigned long long wsel[KNNK];

    for (int r = 0; r < KNNK; ++r) {
        unsigned long long v = tmin;
#pragma unroll
        for (int off = 16; off; off >>= 1)
            v = umin64(v, __shfl_xor_sync(0xffffffffu, v, off));
        if (lane == 0) wmin[w] = v;
        __syncthreads();
        if (tid == 0) {
            unsigned long long bb = wmin[0];
#pragma unroll
            for (int wi = 1; wi < 8; ++wi) bb = umin64(bb, wmin[wi]);
            wsel[r] = bb;
        }
        __syncthreads();
        unsigned long long kk = wsel[r];
        if (tmin == kk) {                     // exactly one owner thread per block
#pragma unroll
            for (int i = 0; i < 8; ++i)
                keys[i] = (keys[i] == kk) ? ~0ull : keys[i];
            tmin = umin64(umin64(umin64(keys[0], keys[1]), umin64(keys[2], keys[3])),
                          umin64(umin64(keys[4], keys[5]), umin64(keys[6], keys[7])));
        }
    }

    if (tid < KNNK) g_idx[bn * KNNK + tid] = (int)(wsel[tid] & 0xffffffffull);
    if (tid < 3 * KNNK) {
        int c = tid >> 4, k = tid & 15;
        int id = (int)(wsel[k] & 0xffffffffull);
        float center = cb[c * NPTS + n];
        float nb = cb[c * NPTS + id];
        dout[LC_OFF + (((size_t)(b * 3 + c) * NPTS) + n) * KNNK + k] = __fsub_rn(center, nb);
    }
}

// ---------- kernel 2: fused gather -> conv1+BN+ReLU -> conv2+BN+ReLU -> max_k ----------
// 256 threads = 8 warps, ONE warp per point; each lane owns 4 consecutive out-channels.
__global__ void __launch_bounds__(256, 1) mlp_kernel(
    const float* __restrict__ w1, const float* __restrict__ w2,
    const float* __restrict__ g1, const float* __restrict__ b1,
    const float* __restrict__ m1, const float* __restrict__ v1,
    const float* __restrict__ g2, const float* __restrict__ b2,
    const float* __restrict__ m2, const float* __restrict__ v2,
    float* __restrict__ dout) {
    extern __shared__ float smem[];
    float* ws1 = smem;                        // [64][128]  ws1[c*128+o] = w1[o][c]
    float* ws2 = ws1 + CINCH * COUTC;         // [128][128] ws2[c*128+o] = w2[o][c]
    unsigned long long* actAll =
        (unsigned long long*)(ws2 + COUTC * COUTC);   // per point: xs 512 u64 + hs 1024 u64

    const int tid = threadIdx.x;
    const int w = tid >> 5, lane = tid & 31;

    for (int i = tid; i < CINCH * COUTC; i += 256) {
        int c = i >> 7, o = i & 127;
        ws1[i] = w1[o * CINCH + c];
    }
    for (int i = tid; i < COUTC * COUTC; i += 256) {
        int c = i >> 7, o = i & 127;
        ws2[i] = w2[o * COUTC + c];
    }

    // BN constants for this thread's 4 consecutive channels (ch = lane*4 + j)
    float s1v[4], c1v[4], s2v[4], c2v[4];
#pragma unroll
    for (int j = 0; j < 4; ++j) {
        int ch = lane * 4 + j;
        float s1 = g1[ch] / sqrtf(v1[ch] + 1e-5f);
        s1v[j] = s1; c1v[j] = b1[ch] - m1[ch] * s1;
        float s2 = g2[ch] / sqrtf(v2[ch] + 1e-5f);
        s2v[j] = s2; c2v[j] = b2[ch] - m2[ch] * s2;
    }
    __syncthreads();

    const int p = blockIdx.x * 8 + w;           // point id 0..16383
    const int b = p >> 11, n = p & (NPTS - 1);
    unsigned long long* xs = actAll + w * (512 + 1024);
    unsigned long long* hs = xs + 512;

    // ---- gather from transposed x: coalesced 256B per neighbor ----
    {
        const int k = lane >> 1, half = lane & 1;
        const int kq = k >> 1, kb = k & 1;
        const int id = __ldg(&g_idx[p * KNNK + k]);
        const float4* xb = (const float4*)(g_xt + ((size_t)b * NPTS + id) * CINCH) + half * 8;
        unsigned* xs32 = (unsigned*)xs;
#pragma unroll
        for (int i = 0; i < 8; ++i) {
            float4 v = __ldg(&xb[i]);
            int c0 = half * 32 + i * 4;
            xs32[SWZ(c0 + 0, kq) * 2 + kb] = __float_as_uint(v.x);
            xs32[SWZ(c0 + 1, kq) * 2 + kb] = __float_as_uint(v.y);
            xs32[SWZ(c0 + 2, kq) * 2 + kb] = __float_as_uint(v.z);
            xs32[SWZ(c0 + 3, kq) * 2 + kb] = __float_as_uint(v.w);
        }
    }
    __syncwarp();

    unsigned long long acc[4][8];
#pragma unroll
    for (int j = 0; j < 4; ++j)
#pragma unroll
        for (int q = 0; q < 8; ++q) acc[j][q] = 0ull;

    // ---- GEMM1: h[ch][k] = sum_c w1[ch][c] * xs[c][k] ----
#pragma unroll 2
    for (int c = 0; c < CINCH; ++c) {
        unsigned long long xv[8];
#pragma unroll
        for (int kq = 0; kq < 8; ++kq) xv[kq] = xs[SWZ(c, kq)];
        float4 wv = *(const float4*)(ws1 + c * COUTC + lane * 4);
        unsigned long long wp0 = pack2(wv.x, wv.x);
        unsigned long long wp1 = pack2(wv.y, wv.y);
        unsigned long long wp2 = pack2(wv.z, wv.z);
        unsigned long long wp3 = pack2(wv.w, wv.w);
#pragma unroll
        for (int kq = 0; kq < 8; ++kq) {
            ffma2(acc[0][kq], wp0, xv[kq]);
            ffma2(acc[1][kq], wp1, xv[kq]);
            ffma2(acc[2][kq], wp2, xv[kq]);
            ffma2(acc[3][kq], wp3, xv[kq]);
        }
    }

    // ---- epilogue 1: BN+ReLU -> hs (swizzled) ----
#pragma unroll
    for (int j = 0; j < 4; ++j) {
        int ch = lane * 4 + j;
#pragma unroll
        for (int kq = 0; kq < 8; ++kq) {
            float lo, hi; unpack2(acc[j][kq], lo, hi);
            lo = fmaxf(fmaf(lo, s1v[j], c1v[j]), 0.f);
            hi = fmaxf(fmaf(hi, s1v[j], c1v[j]), 0.f);
            hs[SWZ(ch, kq)] = pack2(lo, hi);
        }
    }
    __syncwarp();

#pragma unroll
    for (int j = 0; j < 4; ++j)
#pragma unroll
        for (int q = 0; q < 8; ++q) acc[j][q] = 0ull;

    // ---- GEMM2: out[ch][k] = sum_c w2[ch][c] * h[c][k] ----
#pragma unroll 2
    for (int c = 0; c < COUTC; ++c) {
        unsigned long long hv[8];
#pragma unroll
        for (int kq = 0; kq < 8; ++kq) hv[kq] = hs[SWZ(c, kq)];
        float4 wv = *(const float4*)(ws2 + c * COUTC + lane * 4);
        unsigned long long wp0 = pack2(wv.x, wv.x);
        unsigned long long wp1 = pack2(wv.y, wv.y);
        unsigned long long wp2 = pack2(wv.z, wv.z);
        unsigned long long wp3 = pack2(wv.w, wv.w);
#pragma unroll
        for (int kq = 0; kq < 8; ++kq) {
            ffma2(acc[0][kq], wp0, hv[kq]);
            ffma2(acc[1][kq], wp1, hv[kq]);
            ffma2(acc[2][kq], wp2, hv[kq]);
            ffma2(acc[3][kq], wp3, hv[kq]);
        }
    }

    // ---- epilogue 2: BN+ReLU, write knn_mlp_x and y ----
    float* out2 = dout + OUT2_OFF;
#pragma unroll
    for (int j = 0; j < 4; ++j) {
        int ch = lane * 4 + j;
        float4* o4 = (float4*)(out2 + (((size_t)(b * COUTC + ch)) * NPTS + n) * KNNK);
        float mx = 0.f;
#pragma unroll
        for (int q4 = 0; q4 < 4; ++q4) {
            float a0, a1, a2, a3;
            unpack2(acc[j][2 * q4], a0, a1);
            unpack2(acc[j][2 * q4 + 1], a2, a3);
            a0 = fmaxf(fmaf(a0, s2v[j], c2v[j]), 0.f);
            a1 = fmaxf(fmaf(a1, s2v[j], c2v[j]), 0.f);
            a2 = fmaxf(fmaf(a2, s2v[j], c2v[j]), 0.f);
            a3 = fmaxf(fmaf(a3, s2v[j], c2v[j]), 0.f);
            mx = fmaxf(mx, fmaxf(fmaxf(a0, a1), fmaxf(a2, a3)));
            o4[q4] = make_float4(a0, a1, a2, a3);
        }
        dout[(size_t)(b * COUTC + ch) * NPTS + n] = mx;
    }
}

extern "C" void kernel_launch(void* const* d_in, const int* in_sizes, int n_in,
                              void* d_out, int out_size) {
    const float* x      = (const float*)d_in[0];
    const float* coords = (const float*)d_in[1];
    const float* w1     = (const float*)d_in[2];
    const float* g1     = (const float*)d_in[3];
    const float* b1     = (const float*)d_in[4];
    const float* m1     = (const float*)d_in[5];
    const float* v1     = (const float*)d_in[6];
    const float* w2     = (const float*)d_in[7];
    const float* g2     = (const float*)d_in[8];
    const float* b2     = (const float*)d_in[9];
    const float* m2     = (const float*)d_in[10];
    const float* v2     = (const float*)d_in[11];
    float* out = (float*)d_out;

    transpose_kernel<<<dim3(NPTS / 64, BATCH), 256>>>(x);
    knn_kernel<<<BATCH * NPTS, 256>>>(coords, out);

    const int smem_bytes = (CINCH * COUTC + COUTC * COUTC) * 4 + 8 * (512 + 1024) * 8;
    // = 98304 + 98304 = 196608 (192 KB)
    cudaFuncSetAttribute(mlp_kernel, cudaFuncAttributeMaxDynamicSharedMemorySize, smem_bytes);
    mlp_kernel<<<(BATCH * NPTS) / 8, 256, smem_bytes>>>(
        w1, w2, g1, b1, m1, v1, g2, b2, m2, v2, out);
}

// round 6
// speedup vs baseline: 2.0610x; 1.0556x over previous
#include <cuda_runtime.h>

#define NPTS  2048
#define BATCH 8
#define CINCH 64
#define COUTC 128
#define KNNK  16

#define XSTR  132   // padded row stride (floats) for activation tiles

// d_out partitioning (float elements)
constexpr size_t OUT2_OFF = (size_t)BATCH * COUTC * NPTS;                     // 2,097,152
constexpr size_t LC_OFF   = OUT2_OFF + (size_t)BATCH * COUTC * NPTS * KNNK;   // 35,651,584

// scratch (no allocations allowed -> device globals)
__device__ int   g_idx[BATCH * NPTS * KNNK];
__device__ float g_xt[BATCH * NPTS * CINCH];   // x transposed to [b][n][c], 4MB

// ---------- packed fp32x2 helpers ----------
__device__ __forceinline__ unsigned long long pack2(float a, float b) {
    unsigned long long r;
    asm("mov.b64 %0, {%1, %2};" : "=l"(r) : "f"(a), "f"(b));
    return r;
}
__device__ __forceinline__ void unpack2(unsigned long long v, float& a, float& b) {
    asm("mov.b64 {%0, %1}, %2;" : "=f"(a), "=f"(b) : "l"(v));
}
__device__ __forceinline__ void ffma2(unsigned long long& d, unsigned long long a,
                                      unsigned long long b) {
    asm("fma.rn.f32x2 %0, %1, %2, %0;" : "+l"(d) : "l"(a), "l"(b));
}
__device__ __forceinline__ unsigned long long umin64(unsigned long long a,
                                                     unsigned long long b) {
    return a < b ? a : b;
}

// ---------- kernel 0: transpose x[b][c][n] -> g_xt[b][n][c] ----------
__global__ void __launch_bounds__(256) transpose_kernel(const float* __restrict__ x) {
    __shared__ float t[64][65];
    const int b = blockIdx.y, n0 = blockIdx.x * 64;
    const int tid = threadIdx.x;
    const int nn = tid & 63, cq = tid >> 6;          // cq 0..3
#pragma unroll
    for (int i = 0; i < 16; ++i) {
        int c = i * 4 + cq;
        t[c][nn] = x[((size_t)b * CINCH + c) * NPTS + n0 + nn];
    }
    __syncthreads();
    const int nr = tid >> 2, q = tid & 3;            // nr 0..63
    float4* dst = (float4*)(g_xt + ((size_t)b * NPTS + n0 + nr) * CINCH);
#pragma unroll
    for (int i = 0; i < 4; ++i) {
        int c4 = i * 4 + q;                          // 0..15
        dst[c4] = make_float4(t[c4 * 4 + 0][nr], t[c4 * 4 + 1][nr],
                              t[c4 * 4 + 2][nr], t[c4 * 4 + 3][nr]);
    }
}

// ---------- kernel 1: KNN (top-16 ascending d2, tie -> smaller index) + local coords ----
__global__ void __launch_bounds__(256) knn_kernel(const float* __restrict__ coords,
                                                  float* __restrict__ dout) {
    const int bn = blockIdx.x;                 // 0..16383
    const int b = bn >> 11, n = bn & (NPTS - 1);
    const int tid = threadIdx.x;               // 256 threads
    const int w = tid >> 5, lane = tid & 31;
    const float* cb = coords + (size_t)b * 3 * NPTS;
    const float qx = cb[n], qy = cb[NPTS + n], qz = cb[2 * NPTS + n];
    const float sqn = __fadd_rn(__fadd_rn(__fmul_rn(qx, qx), __fmul_rn(qy, qy)),
                                __fmul_rn(qz, qz));

    unsigned long long keys[8];
#pragma unroll
    for (int i = 0; i < 8; ++i) {
        int m = tid + (i << 8);
        float mx = cb[m], my = cb[NPTS + m], mz = cb[2 * NPTS + m];
        float sqm = __fadd_rn(__fadd_rn(__fmul_rn(mx, mx), __fmul_rn(my, my)),
                              __fmul_rn(mz, mz));
        float dot = fmaf(qz, mz, fmaf(qy, my, __fmul_rn(qx, mx)));
        float t  = __fadd_rn(sqn, sqm);
        float d2 = __fsub_rn(t, __fmul_rn(2.0f, dot));
        unsigned u = __float_as_uint(d2);
        u = (u & 0x80000000u) ? ~u : (u | 0x80000000u);   // sortable float bits
        keys[i] = ((unsigned long long)u << 32) | (unsigned)m;
    }

    unsigned long long tmin =
        umin64(umin64(umin64(keys[0], keys[1]), umin64(keys[2], keys[3])),
               umin64(umin64(keys[4], keys[5]), umin64(keys[6], keys[7])));

    __shared__ unsigned long long wmin[8];
    __shared__ unsigned long long wsel[KNNK];

    for (int r = 0; r < KNNK; ++r) {
        unsigned long long v = tmin;
#pragma unroll
        for (int off = 16; off; off >>= 1)
            v = umin64(v, __shfl_xor_sync(0xffffffffu, v, off));
        if (lane == 0) wmin[w] = v;
        __syncthreads();
        if (tid == 0) {
            unsigned long long bb = wmin[0];
#pragma unroll
            for (int wi = 1; wi < 8; ++wi) bb = umin64(bb, wmin[wi]);
            wsel[r] = bb;
        }
        __syncthreads();
        unsigned long long kk = wsel[r];
        if (tmin == kk) {                     // exactly one owner thread per block
#pragma unroll
            for (int i = 0; i < 8; ++i)
                keys[i] = (keys[i] == kk) ? ~0ull : keys[i];
            tmin = umin64(umin64(umin64(keys[0], keys[1]), umin64(keys[2], keys[3])),
                          umin64(umin64(keys[4], keys[5]), umin64(keys[6], keys[7])));
        }
    }

    if (tid < KNNK) g_idx[bn * KNNK + tid] = (int)(wsel[tid] & 0xffffffffull);
    if (tid < 3 * KNNK) {
        int c = tid >> 4, k = tid & 15;
        int id = (int)(wsel[k] & 0xffffffffull);
        float center = cb[c * NPTS + n];
        float nb = cb[c * NPTS + id];
        dout[LC_OFF + (((size_t)(b * 3 + c) * NPTS) + n) * KNNK + k] = __fsub_rn(center, nb);
    }
}

// ---------- kernel 2: register-tiled fused MLP ----------
// Block = 256 threads (16x16), 8 points = 128 columns (col = pp*16 + k).
// Each thread computes an 8x8 tile: o = ty*8.., col = tx*8..
__global__ void __launch_bounds__(256, 1) mlp_kernel(
    const float* __restrict__ w1, const float* __restrict__ w2,
    const float* __restrict__ g1, const float* __restrict__ b1,
    const float* __restrict__ m1, const float* __restrict__ v1,
    const float* __restrict__ g2, const float* __restrict__ b2,
    const float* __restrict__ m2, const float* __restrict__ v2,
    float* __restrict__ dout) {
    extern __shared__ float smem[];
    float* ws1 = smem;                        // [64][128]  ws1[c*128+o] = w1[o][c]
    float* ws2 = ws1 + CINCH * COUTC;         // [128][128] ws2[c*128+o] = w2[o][c]
    float* xs  = ws2 + COUTC * COUTC;         // [64][XSTR]
    float* hs  = xs + CINCH * XSTR;           // [128][XSTR]

    const int tid = threadIdx.x;
    const int tx = tid & 15, ty = tid >> 4;

    for (int i = tid; i < CINCH * COUTC; i += 256) {
        int c = i >> 7, o = i & 127;
        ws1[i] = w1[o * CINCH + c];
    }
    for (int i = tid; i < COUTC * COUTC; i += 256) {
        int c = i >> 7, o = i & 127;
        ws2[i] = w2[o * COUTC + c];
    }

    // BN constants for this thread's 8 o-rows (ch = ty*8 + j)
    float s1v[8], c1v[8], s2v[8], c2v[8];
#pragma unroll
    for (int j = 0; j < 8; ++j) {
        int ch = ty * 8 + j;
        float s1 = g1[ch] / sqrtf(v1[ch] + 1e-5f);
        s1v[j] = s1; c1v[j] = b1[ch] - m1[ch] * s1;
        float s2 = g2[ch] / sqrtf(v2[ch] + 1e-5f);
        s2v[j] = s2; c2v[j] = b2[ch] - m2[ch] * s2;
    }

    const int bIdx = blockIdx.x >> 8;                 // batch
    const int n0   = (blockIdx.x & 255) * 8;          // first point index in batch

    // ---- gather: xs[c][col] = x_t[b][idx[col]][c]; 2 threads per column ----
    {
        const int col = tid >> 1, half = tid & 1;
        const int id = __ldg(&g_idx[blockIdx.x * 128 + col]);
        const float4* src =
            (const float4*)(g_xt + ((size_t)bIdx * NPTS + id) * CINCH) + half * 8;
#pragma unroll
        for (int i = 0; i < 8; ++i) {
            float4 v = __ldg(&src[i]);
            int c = half * 32 + i * 4;
            xs[(c + 0) * XSTR + col] = v.x;
            xs[(c + 1) * XSTR + col] = v.y;
            xs[(c + 2) * XSTR + col] = v.z;
            xs[(c + 3) * XSTR + col] = v.w;
        }
    }
    __syncthreads();

    unsigned long long acc[8][4];
#pragma unroll
    for (int j = 0; j < 8; ++j)
#pragma unroll
        for (int q = 0; q < 4; ++q) acc[j][q] = 0ull;

    // ---- GEMM1: h[o][col] = sum_c w1[o][c] * xs[c][col] ----
#pragma unroll 4
    for (int c = 0; c < CINCH; ++c) {
        const float4 a0 = *(const float4*)(ws1 + c * COUTC + ty * 8);
        const float4 a1 = *(const float4*)(ws1 + c * COUTC + ty * 8 + 4);
        const ulonglong2 b0 = *(const ulonglong2*)(xs + c * XSTR + tx * 8);
        const ulonglong2 b1v = *(const ulonglong2*)(xs + c * XSTR + tx * 8 + 4);
        unsigned long long w0 = pack2(a0.x, a0.x), w1p = pack2(a0.y, a0.y);
        unsigned long long w2p = pack2(a0.z, a0.z), w3 = pack2(a0.w, a0.w);
        unsigned long long w4 = pack2(a1.x, a1.x), w5 = pack2(a1.y, a1.y);
        unsigned long long w6 = pack2(a1.z, a1.z), w7 = pack2(a1.w, a1.w);
        ffma2(acc[0][0], w0, b0.x); ffma2(acc[0][1], w0, b0.y);
        ffma2(acc[0][2], w0, b1v.x); ffma2(acc[0][3], w0, b1v.y);
        ffma2(acc[1][0], w1p, b0.x); ffma2(acc[1][1], w1p, b0.y);
        ffma2(acc[1][2], w1p, b1v.x); ffma2(acc[1][3], w1p, b1v.y);
        ffma2(acc[2][0], w2p, b0.x); ffma2(acc[2][1], w2p, b0.y);
        ffma2(acc[2][2], w2p, b1v.x); ffma2(acc[2][3], w2p, b1v.y);
        ffma2(acc[3][0], w3, b0.x); ffma2(acc[3][1], w3, b0.y);
        ffma2(acc[3][2], w3, b1v.x); ffma2(acc[3][3], w3, b1v.y);
        ffma2(acc[4][0], w4, b0.x); ffma2(acc[4][1], w4, b0.y);
        ffma2(acc[4][2], w4, b1v.x); ffma2(acc[4][3], w4, b1v.y);
        ffma2(acc[5][0], w5, b0.x); ffma2(acc[5][1], w5, b0.y);
        ffma2(acc[5][2], w5, b1v.x); ffma2(acc[5][3], w5, b1v.y);
        ffma2(acc[6][0], w6, b0.x); ffma2(acc[6][1], w6, b0.y);
        ffma2(acc[6][2], w6, b1v.x); ffma2(acc[6][3], w6, b1v.y);
        ffma2(acc[7][0], w7, b0.x); ffma2(acc[7][1], w7, b0.y);
        ffma2(acc[7][2], w7, b1v.x); ffma2(acc[7][3], w7, b1v.y);
    }

    // ---- epilogue 1: BN+ReLU -> hs[o][col] ----
#pragma unroll
    for (int j = 0; j < 8; ++j) {
        int o = ty * 8 + j;
#pragma unroll
        for (int q = 0; q < 4; ++q) {
            float lo, hi; unpack2(acc[j][q], lo, hi);
            lo = fmaxf(fmaf(lo, s1v[j], c1v[j]), 0.f);
            hi = fmaxf(fmaf(hi, s1v[j], c1v[j]), 0.f);
            *(float2*)(hs + o * XSTR + tx * 8 + q * 2) = make_float2(lo, hi);
        }
    }
    __syncthreads();

#pragma unroll
    for (int j = 0; j < 8; ++j)
#pragma unroll
        for (int q = 0; q < 4; ++q) acc[j][q] = 0ull;

    // ---- GEMM2: out[o][col] = sum_c w2[o][c] * hs[c][col] ----
#pragma unroll 4
    for (int c = 0; c < COUTC; ++c) {
        const float4 a0 = *(const float4*)(ws2 + c * COUTC + ty * 8);
        const float4 a1 = *(const float4*)(ws2 + c * COUTC + ty * 8 + 4);
        const ulonglong2 b0 = *(const ulonglong2*)(hs + c * XSTR + tx * 8);
        const ulonglong2 b1v = *(const ulonglong2*)(hs + c * XSTR + tx * 8 + 4);
        unsigned long long w0 = pack2(a0.x, a0.x), w1p = pack2(a0.y, a0.y);
        unsigned long long w2p = pack2(a0.z, a0.z), w3 = pack2(a0.w, a0.w);
        unsigned long long w4 = pack2(a1.x, a1.x), w5 = pack2(a1.y, a1.y);
        unsigned long long w6 = pack2(a1.z, a1.z), w7 = pack2(a1.w, a1.w);
        ffma2(acc[0][0], w0, b0.x); ffma2(acc[0][1], w0, b0.y);
        ffma2(acc[0][2], w0, b1v.x); ffma2(acc[0][3], w0, b1v.y);
        ffma2(acc[1][0], w1p, b0.x); ffma2(acc[1][1], w1p, b0.y);
        ffma2(acc[1][2], w1p, b1v.x); ffma2(acc[1][3], w1p, b1v.y);
        ffma2(acc[2][0], w2p, b0.x); ffma2(acc[2][1], w2p, b0.y);
        ffma2(acc[2][2], w2p, b1v.x); ffma2(acc[2][3], w2p, b1v.y);
        ffma2(acc[3][0], w3, b0.x); ffma2(acc[3][1], w3, b0.y);
        ffma2(acc[3][2], w3, b1v.x); ffma2(acc[3][3], w3, b1v.y);
        ffma2(acc[4][0], w4, b0.x); ffma2(acc[4][1], w4, b0.y);
        ffma2(acc[4][2], w4, b1v.x); ffma2(acc[4][3], w4, b1v.y);
        ffma2(acc[5][0], w5, b0.x); ffma2(acc[5][1], w5, b0.y);
        ffma2(acc[5][2], w5, b1v.x); ffma2(acc[5][3], w5, b1v.y);
        ffma2(acc[6][0], w6, b0.x); ffma2(acc[6][1], w6, b0.y);
        ffma2(acc[6][2], w6, b1v.x); ffma2(acc[6][3], w6, b1v.y);
        ffma2(acc[7][0], w7, b0.x); ffma2(acc[7][1], w7, b0.y);
        ffma2(acc[7][2], w7, b1v.x); ffma2(acc[7][3], w7, b1v.y);
    }

    // ---- epilogue 2: BN+ReLU, write knn_mlp_x and y ----
    // thread's cols = tx*8..+8 = k-half (tx&1) of point pp = tx>>1
    const int pp = tx >> 1, k0 = (tx & 1) * 8;
    const int n = n0 + pp;
    float* out2 = dout + OUT2_OFF;
#pragma unroll
    for (int j = 0; j < 8; ++j) {
        int ch = ty * 8 + j;
        float a[8];
        float mx = 0.f;
#pragma unroll
        for (int q = 0; q < 4; ++q) {
            float lo, hi; unpack2(acc[j][q], lo, hi);
            lo = fmaxf(fmaf(lo, s2v[j], c2v[j]), 0.f);
            hi = fmaxf(fmaf(hi, s2v[j], c2v[j]), 0.f);
            a[2 * q] = lo; a[2 * q + 1] = hi;
            mx = fmaxf(mx, fmaxf(lo, hi));
        }
        float* obase = out2 + (((size_t)(bIdx * COUTC + ch)) * NPTS + n) * KNNK + k0;
        *(float4*)obase       = make_float4(a[0], a[1], a[2], a[3]);
        *(float4*)(obase + 4) = make_float4(a[4], a[5], a[6], a[7]);
        // combine the two k-halves for y
        float other = __shfl_xor_sync(0xffffffffu, mx, 1);
        if ((tx & 1) == 0)
            dout[(size_t)(bIdx * COUTC + ch) * NPTS + n] = fmaxf(mx, other);
    }
}

extern "C" void kernel_launch(void* const* d_in, const int* in_sizes, int n_in,
                              void* d_out, int out_size) {
    const float* x      = (const float*)d_in[0];
    const float* coords = (const float*)d_in[1];
    const float* w1     = (const float*)d_in[2];
    const float* g1     = (const float*)d_in[3];
    const float* b1     = (const float*)d_in[4];
    const float* m1     = (const float*)d_in[5];
    const float* v1     = (const float*)d_in[6];
    const float* w2     = (const float*)d_in[7];
    const float* g2     = (const float*)d_in[8];
    const float* b2     = (const float*)d_in[9];
    const float* m2     = (const float*)d_in[10];
    const float* v2     = (const float*)d_in[11];
    float* out = (float*)d_out;

    transpose_kernel<<<dim3(NPTS / 64, BATCH), 256>>>(x);
    knn_kernel<<<BATCH * NPTS, 256>>>(coords, out);

    const int smem_bytes = (CINCH * COUTC + COUTC * COUTC
                          + CINCH * XSTR + COUTC * XSTR) * 4;   // 199,680 B
    cudaFuncSetAttribute(mlp_kernel, cudaFuncAttributeMaxDynamicSharedMemorySize, smem_bytes);
    mlp_kernel<<<(BATCH * NPTS) / 8, 256, smem_bytes>>>(
        w1, w2, g1, b1, m1, v1, g2, b2, m2, v2, out);
}

// round 12
// speedup vs baseline: 2.5285x; 1.2268x over previous
#include <cuda_runtime.h>
#include <cstdint>

#define NPTS  2048
#define BATCH 8
#define CINCH 64
#define COUTC 128
#define KNNK  16

// d_out partitioning (float elements)
constexpr size_t OUT2_OFF = (size_t)BATCH * COUTC * NPTS;                     // 2,097,152
constexpr size_t LC_OFF   = OUT2_OFF + (size_t)BATCH * COUTC * NPTS * KNNK;   // 35,651,584

__device__ int   g_idx[BATCH * NPTS * KNNK];
__device__ float g_xt[BATCH * NPTS * CINCH];   // x transposed to [b][n][c]

__device__ __forceinline__ unsigned long long umin64(unsigned long long a,
                                                     unsigned long long b) {
    return a < b ? a : b;
}
__device__ __forceinline__ uint32_t f2u(float x) { return __float_as_uint(x); }
__device__ __forceinline__ float u2f(uint32_t x) { return __uint_as_float(x); }

__device__ __forceinline__ uint32_t f2tf32(float x) {
    uint32_t r; asm("cvt.rna.tf32.f32 %0, %1;" : "=r"(r) : "f"(x)); return r;
}
__device__ __forceinline__ void tf32split(float v, uint32_t& hi, uint32_t& lo) {
    hi = f2tf32(v);
    lo = f2tf32(v - u2f(hi));
}
#define MMA_TF32(c, a0, a1, a2, a3, b0, b1)                                      \
    asm volatile(                                                                \
        "mma.sync.aligned.m16n8k8.row.col.f32.tf32.tf32.f32 "                    \
        "{%0,%1,%2,%3}, {%4,%5,%6,%7}, {%8,%9}, {%0,%1,%2,%3};"                  \
        : "+f"((c)[0]), "+f"((c)[1]), "+f"((c)[2]), "+f"((c)[3])                 \
        : "r"(a0), "r"(a1), "r"(a2), "r"(a3), "r"(b0), "r"(b1))

// ---------- kernel 0: transpose x[b][c][n] -> g_xt[b][n][c] ----------
__global__ void __launch_bounds__(256) transpose_kernel(const float* __restrict__ x) {
    __shared__ float t[64][65];
    const int b = blockIdx.y, n0 = blockIdx.x * 64;
    const int tid = threadIdx.x;
    const int nn = tid & 63, cq = tid >> 6;
#pragma unroll
    for (int i = 0; i < 16; ++i) {
        int c = i * 4 + cq;
        t[c][nn] = x[((size_t)b * CINCH + c) * NPTS + n0 + nn];
    }
    __syncthreads();
    const int nr = tid >> 2, q = tid & 3;
    float4* dst = (float4*)(g_xt + ((size_t)b * NPTS + n0 + nr) * CINCH);
#pragma unroll
    for (int i = 0; i < 4; ++i) {
        int c4 = i * 4 + q;
        dst[c4] = make_float4(t[c4 * 4 + 0][nr], t[c4 * 4 + 1][nr],
                              t[c4 * 4 + 2][nr], t[c4 * 4 + 3][nr]);
    }
}

// ---------- kernel 1: KNN (top-16 ascending d2, tie -> smaller index) + local coords ----
__global__ void __launch_bounds__(256) knn_kernel(const float* __restrict__ coords,
                                                  float* __restrict__ dout) {
    const int bn = blockIdx.x;
    const int b = bn >> 11, n = bn & (NPTS - 1);
    const int tid = threadIdx.x;
    const int w = tid >> 5, lane = tid & 31;
    const float* cb = coords + (size_t)b * 3 * NPTS;
    const float qx = cb[n], qy = cb[NPTS + n], qz = cb[2 * NPTS + n];
    const float sqn = __fadd_rn(__fadd_rn(__fmul_rn(qx, qx), __fmul_rn(qy, qy)),
                                __fmul_rn(qz, qz));

    unsigned long long keys[8];
#pragma unroll
    for (int i = 0; i < 8; ++i) {
        int m = tid + (i << 8);
        float mx = cb[m], my = cb[NPTS + m], mz = cb[2 * NPTS + m];
        float sqm = __fadd_rn(__fadd_rn(__fmul_rn(mx, mx), __fmul_rn(my, my)),
                              __fmul_rn(mz, mz));
        float dot = fmaf(qz, mz, fmaf(qy, my, __fmul_rn(qx, mx)));
        float t  = __fadd_rn(sqn, sqm);
        float d2 = __fsub_rn(t, __fmul_rn(2.0f, dot));
        unsigned u = __float_as_uint(d2);
        u = (u & 0x80000000u) ? ~u : (u | 0x80000000u);
        keys[i] = ((unsigned long long)u << 32) | (unsigned)m;
    }

    unsigned long long tmin =
        umin64(umin64(umin64(keys[0], keys[1]), umin64(keys[2], keys[3])),
               umin64(umin64(keys[4], keys[5]), umin64(keys[6], keys[7])));

    __shared__ unsigned long long wmin[8];
    __shared__ unsigned long long wsel[KNNK];

    for (int r = 0; r < KNNK; ++r) {
        unsigned long long v = tmin;
#pragma unroll
        for (int off = 16; off; off >>= 1)
            v = umin64(v, __shfl_xor_sync(0xffffffffu, v, off));
        if (lane == 0) wmin[w] = v;
        __syncthreads();
        if (tid == 0) {
            unsigned long long bb = wmin[0];
#pragma unroll
            for (int wi = 1; wi < 8; ++wi) bb = umin64(bb, wmin[wi]);
            wsel[r] = bb;
        }
        __syncthreads();
        unsigned long long kk = wsel[r];
        if (tmin == kk) {
#pragma unroll
            for (int i = 0; i < 8; ++i)
                keys[i] = (keys[i] == kk) ? ~0ull : keys[i];
            tmin = umin64(umin64(umin64(keys[0], keys[1]), umin64(keys[2], keys[3])),
                          umin64(umin64(keys[4], keys[5]), umin64(keys[6], keys[7])));
        }
    }

    if (tid < KNNK) g_idx[bn * KNNK + tid] = (int)(wsel[tid] & 0xffffffffull);
    if (tid < 3 * KNNK) {
        int c = tid >> 4, k = tid & 15;
        int id = (int)(wsel[k] & 0xffffffffull);
        float center = cb[c * NPTS + n];
        float nb = cb[c * NPTS + id];
        dout[LC_OFF + (((size_t)(b * 3 + c) * NPTS) + n) * KNNK + k] = __fsub_rn(center, nb);
    }
}

// ---------- kernel 2: mma.sync 3xTF32 fused MLP ----------
// 4096 CTAs x 256 thr. Tile = 4 points = 64 cols. Warp w: rows o = 16w..16w+15.
// SMEM: W1 hi/lo [128][stride 68], X hi/lo [64][stride 72], HS hi/lo [128][stride 72].
// W2 hi/lo lives in registers (per-thread A-frags for all 16 k-steps).
#define W1STR 68
#define ASTR  72
__global__ void __launch_bounds__(256, 1) mlp_mma_kernel(
    const float* __restrict__ w1, const float* __restrict__ w2,
    const float* __restrict__ g1, const float* __restrict__ b1,
    const float* __restrict__ m1, const float* __restrict__ v1,
    const float* __restrict__ g2, const float* __restrict__ b2,
    const float* __restrict__ m2, const float* __restrict__ v2,
    float* __restrict__ dout) {
    extern __shared__ float sm[];
    float* W1HI = sm;                       //  8704 floats
    float* W1LO = sm + 8704;                //  8704
    float* XHI  = sm + 17408;               //  4608
    float* XLO  = sm + 22016;               //  4608
    float* HSHI = sm + 26624;               //  9216
    float* HSLO = sm + 35840;               //  9216  -> total 45056 floats

    const int tid = threadIdx.x;
    const int w = tid >> 5, lane = tid & 31;
    const int gid = lane >> 2, tig = lane & 3;
    const int rA = w * 16 + gid, rB = rA + 8;

    // ---- prologue: W1 -> SMEM (hi/lo) ----
    {
        const int o = tid >> 1, ch = (tid & 1) * 32;
        const float4* src = (const float4*)(w1 + o * CINCH + ch);
#pragma unroll
        for (int i = 0; i < 8; ++i) {
            float4 v = src[i];
            int c = ch + i * 4;
            uint32_t h, l;
            tf32split(v.x, h, l); W1HI[o * W1STR + c + 0] = u2f(h); W1LO[o * W1STR + c + 0] = u2f(l);
            tf32split(v.y, h, l); W1HI[o * W1STR + c + 1] = u2f(h); W1LO[o * W1STR + c + 1] = u2f(l);
            tf32split(v.z, h, l); W1HI[o * W1STR + c + 2] = u2f(h); W1LO[o * W1STR + c + 2] = u2f(l);
            tf32split(v.w, h, l); W1HI[o * W1STR + c + 3] = u2f(h); W1LO[o * W1STR + c + 3] = u2f(l);
        }
    }

    // ---- prologue: W2 -> register A-frags (hi/lo), 16 k-steps ----
    uint32_t a2h[16][4], a2l[16][4];
#pragma unroll
    for (int s = 0; s < 16; ++s) {
        tf32split(w2[rA * COUTC + s * 8 + tig],     a2h[s][0], a2l[s][0]);
        tf32split(w2[rB * COUTC + s * 8 + tig],     a2h[s][1], a2l[s][1]);
        tf32split(w2[rA * COUTC + s * 8 + tig + 4], a2h[s][2], a2l[s][2]);
        tf32split(w2[rB * COUTC + s * 8 + tig + 4], a2h[s][3], a2l[s][3]);
    }

    // BN constants for rows rA, rB
    const float s1A = g1[rA] / sqrtf(v1[rA] + 1e-5f);
    const float c1A = b1[rA] - m1[rA] * s1A;
    const float s1B = g1[rB] / sqrtf(v1[rB] + 1e-5f);
    const float c1B = b1[rB] - m1[rB] * s1B;
    const float s2A = g2[rA] / sqrtf(v2[rA] + 1e-5f);
    const float c2A = b2[rA] - m2[rA] * s2A;
    const float s2B = g2[rB] / sqrtf(v2[rB] + 1e-5f);
    const float c2B = b2[rB] - m2[rB] * s2B;

    const int tile = blockIdx.x;                // 0..4095
    const int bIdx = tile >> 9;                 // 512 tiles per batch
    const int np0  = (tile & 511) * 4;          // first point (in-batch)

    // ---- gather + split: X[c][col], col = pp*16 + k ----
    {
        const int col = tid >> 2, q = tid & 3;
        const int id = __ldg(&g_idx[tile * 64 + col]);
        const float4* src =
            (const float4*)(g_xt + ((size_t)bIdx * NPTS + id) * CINCH) + q * 4;
#pragma unroll
        for (int i = 0; i < 4; ++i) {
            float4 v = __ldg(&src[i]);
            int c = q * 16 + i * 4;
            uint32_t h, l;
            tf32split(v.x, h, l); XHI[(c + 0) * ASTR + col] = u2f(h); XLO[(c + 0) * ASTR + col] = u2f(l);
            tf32split(v.y, h, l); XHI[(c + 1) * ASTR + col] = u2f(h); XLO[(c + 1) * ASTR + col] = u2f(l);
            tf32split(v.z, h, l); XHI[(c + 2) * ASTR + col] = u2f(h); XLO[(c + 2) * ASTR + col] = u2f(l);
            tf32split(v.w, h, l); XHI[(c + 3) * ASTR + col] = u2f(h); XLO[(c + 3) * ASTR + col] = u2f(l);
        }
    }
    __syncthreads();

    float acc[8][4];
#pragma unroll
    for (int nt = 0; nt < 8; ++nt)
#pragma unroll
        for (int j = 0; j < 4; ++j) acc[nt][j] = 0.f;

    // ---- GEMM1: D1 = W1 (m=o, k=c) x X (k=c, n=col); K = 64 ----
#pragma unroll
    for (int s = 0; s < 8; ++s) {
        const int k0 = s * 8;
        uint32_t A0h = f2u(W1HI[rA * W1STR + k0 + tig]);
        uint32_t A1h = f2u(W1HI[rB * W1STR + k0 + tig]);
        uint32_t A2h = f2u(W1HI[rA * W1STR + k0 + tig + 4]);
        uint32_t A3h = f2u(W1HI[rB * W1STR + k0 + tig + 4]);
        uint32_t A0l = f2u(W1LO[rA * W1STR + k0 + tig]);
        uint32_t A1l = f2u(W1LO[rB * W1STR + k0 + tig]);
        uint32_t A2l = f2u(W1LO[rA * W1STR + k0 + tig + 4]);
        uint32_t A3l = f2u(W1LO[rB * W1STR + k0 + tig + 4]);
#pragma unroll
        for (int nt = 0; nt < 8; ++nt) {
            uint32_t B0h = f2u(XHI[(k0 + tig) * ASTR + nt * 8 + gid]);
            uint32_t B1h = f2u(XHI[(k0 + tig + 4) * ASTR + nt * 8 + gid]);
            uint32_t B0l = f2u(XLO[(k0 + tig) * ASTR + nt * 8 + gid]);
            uint32_t B1l = f2u(XLO[(k0 + tig + 4) * ASTR + nt * 8 + gid]);
            MMA_TF32(acc[nt], A0h, A1h, A2h, A3h, B0h, B1h);
            MMA_TF32(acc[nt], A0h, A1h, A2h, A3h, B0l, B1l);
            MMA_TF32(acc[nt], A0l, A1l, A2l, A3l, B0h, B1h);
        }
    }

    // ---- epilogue 1: BN+ReLU -> HS (hi/lo) ----
#pragma unroll
    for (int nt = 0; nt < 8; ++nt) {
        float h0 = fmaxf(fmaf(acc[nt][0], s1A, c1A), 0.f);
        float h1 = fmaxf(fmaf(acc[nt][1], s1A, c1A), 0.f);
        float h2 = fmaxf(fmaf(acc[nt][2], s1B, c1B), 0.f);
        float h3 = fmaxf(fmaf(acc[nt][3], s1B, c1B), 0.f);
        int colp = nt * 8 + 2 * tig;
        uint32_t h, l;
        tf32split(h0, h, l); HSHI[rA * ASTR + colp]     = u2f(h); HSLO[rA * ASTR + colp]     = u2f(l);
        tf32split(h1, h, l); HSHI[rA * ASTR + colp + 1] = u2f(h); HSLO[rA * ASTR + colp + 1] = u2f(l);
        tf32split(h2, h, l); HSHI[rB * ASTR + colp]     = u2f(h); HSLO[rB * ASTR + colp]     = u2f(l);
        tf32split(h3, h, l); HSHI[rB * ASTR + colp + 1] = u2f(h); HSLO[rB * ASTR + colp + 1] = u2f(l);
    }
    __syncthreads();

#pragma unroll
    for (int nt = 0; nt < 8; ++nt)
#pragma unroll
        for (int j = 0; j < 4; ++j) acc[nt][j] = 0.f;

    // ---- GEMM2: D2 = W2 (regs) x HS; K = 128 ----
#pragma unroll
    for (int s = 0; s < 16; ++s) {
        const int k0 = s * 8;
#pragma unroll
        for (int nt = 0; nt < 8; ++nt) {
            uint32_t B0h = f2u(HSHI[(k0 + tig) * ASTR + nt * 8 + gid]);
            uint32_t B1h = f2u(HSHI[(k0 + tig + 4) * ASTR + nt * 8 + gid]);
            uint32_t B0l = f2u(HSLO[(k0 + tig) * ASTR + nt * 8 + gid]);
            uint32_t B1l = f2u(HSLO[(k0 + tig + 4) * ASTR + nt * 8 + gid]);
            MMA_TF32(acc[nt], a2h[s][0], a2h[s][1], a2h[s][2], a2h[s][3], B0h, B1h);
            MMA_TF32(acc[nt], a2h[s][0], a2h[s][1], a2h[s][2], a2h[s][3], B0l, B1l);
            MMA_TF32(acc[nt], a2l[s][0], a2l[s][1], a2l[s][2], a2l[s][3], B0h, B1h);
        }
    }

    // ---- epilogue 2: BN+ReLU, write knn_mlp_x + y ----
    float* out2 = dout + OUT2_OFF;
    float pmA[4], pmB[4];
#pragma unroll
    for (int pp = 0; pp < 4; ++pp) { pmA[pp] = 0.f; pmB[pp] = 0.f; }

#pragma unroll
    for (int nt = 0; nt < 8; ++nt) {
        float v0 = fmaxf(fmaf(acc[nt][0], s2A, c2A), 0.f);
        float v1 = fmaxf(fmaf(acc[nt][1], s2A, c2A), 0.f);
        float v2_ = fmaxf(fmaf(acc[nt][2], s2B, c2B), 0.f);
        float v3 = fmaxf(fmaf(acc[nt][3], s2B, c2B), 0.f);
        const int pp = nt >> 1;
        const int kk = (nt & 1) * 8 + 2 * tig;
        pmA[pp] = fmaxf(pmA[pp], fmaxf(v0, v1));
        pmB[pp] = fmaxf(pmB[pp], fmaxf(v2_, v3));
        const int n = np0 + pp;
        float* pA = out2 + (((size_t)(bIdx * COUTC + rA)) * NPTS + n) * KNNK + kk;
        float* pB = out2 + (((size_t)(bIdx * COUTC + rB)) * NPTS + n) * KNNK + kk;
        *(float2*)pA = make_float2(v0, v1);
        *(float2*)pB = make_float2(v2_, v3);
    }
#pragma unroll
    for (int pp = 0; pp < 4; ++pp) {
        float mA = pmA[pp], mB = pmB[pp];
        mA = fmaxf(mA, __shfl_xor_sync(0xffffffffu, mA, 1));
        mA = fmaxf(mA, __shfl_xor_sync(0xffffffffu, mA, 2));
        mB = fmaxf(mB, __shfl_xor_sync(0xffffffffu, mB, 1));
        mB = fmaxf(mB, __shfl_xor_sync(0xffffffffu, mB, 2));
        if (tig == 0) {
            const int n = np0 + pp;
            dout[(size_t)(bIdx * COUTC + rA) * NPTS + n] = mA;
            dout[(size_t)(bIdx * COUTC + rB) * NPTS + n] = mB;
        }
    }
}

extern "C" void kernel_launch(void* const* d_in, const int* in_sizes, int n_in,
                              void* d_out, int out_size) {
    const float* x      = (const float*)d_in[0];
    const float* coords = (const float*)d_in[1];
    const float* w1     = (const float*)d_in[2];
    const float* g1     = (const float*)d_in[3];
    const float* b1     = (const float*)d_in[4];
    const float* m1     = (const float*)d_in[5];
    const float* v1     = (const float*)d_in[6];
    const float* w2     = (const float*)d_in[7];
    const float* g2     = (const float*)d_in[8];
    const float* b2     = (const float*)d_in[9];
    const float* m2     = (const float*)d_in[10];
    const float* v2     = (const float*)d_in[11];
    float* out = (float*)d_out;

    transpose_kernel<<<dim3(NPTS / 64, BATCH), 256>>>(x);
    knn_kernel<<<BATCH * NPTS, 256>>>(coords, out);

    const int smem_bytes = 45056 * 4;   // 180,224 B
    cudaFuncSetAttribute(mlp_mma_kernel, cudaFuncAttributeMaxDynamicSharedMemorySize, smem_bytes);
    mlp_mma_kernel<<<(BATCH * NPTS) / 4, 256, smem_bytes>>>(
        w1, w2, g1, b1, m1, v1, g2, b2, m2, v2, out);
}

// round 14
// speedup vs baseline: 4.0222x; 1.5907x over previous
#include <cuda_runtime.h>
#include <cuda_fp16.h>
#include <cstdint>

#define NPTS  2048
#define BATCH 8
#define CINCH 64
#define COUTC 128
#define KNNK  16
#define NTILES 2048   // 8 points per tile

// d_out partitioning (float elements)
constexpr size_t OUT2_OFF = (size_t)BATCH * COUTC * NPTS;                     // 2,097,152
constexpr size_t LC_OFF   = OUT2_OFF + (size_t)BATCH * COUTC * NPTS * KNNK;   // 35,651,584

__device__ int   g_idx[BATCH * NPTS * KNNK];
__device__ float g_xt[BATCH * NPTS * CINCH];   // x transposed to [b][n][c]

__device__ __forceinline__ unsigned long long umin64(unsigned long long a,
                                                     unsigned long long b) {
    return a < b ? a : b;
}

__device__ __forceinline__ uint32_t packh2(__half a, __half b) {
    return (uint32_t)__half_as_ushort(a) | ((uint32_t)__half_as_ushort(b) << 16);
}
// fp16 hi/lo split of two floats -> packed hi pair, lo pair
__device__ __forceinline__ void h2split(float a, float b, uint32_t& hi, uint32_t& lo) {
    __half ah = __float2half_rn(a), bh = __float2half_rn(b);
    __half al = __float2half_rn(a - __half2float(ah));
    __half bl = __float2half_rn(b - __half2float(bh));
    hi = packh2(ah, bh);
    lo = packh2(al, bl);
}
__device__ __forceinline__ void hsplit(float a, __half& h, __half& l) {
    h = __float2half_rn(a);
    l = __float2half_rn(a - __half2float(h));
}

#define MMA_F16(c, a0, a1, a2, a3, b0, b1)                                       \
    asm volatile(                                                                \
        "mma.sync.aligned.m16n8k16.row.col.f32.f16.f16.f32 "                     \
        "{%0,%1,%2,%3}, {%4,%5,%6,%7}, {%8,%9}, {%0,%1,%2,%3};"                  \
        : "+f"((c)[0]), "+f"((c)[1]), "+f"((c)[2]), "+f"((c)[3])                 \
        : "r"(a0), "r"(a1), "r"(a2), "r"(a3), "r"(b0), "r"(b1))

// ---------- kernel 0: transpose x[b][c][n] -> g_xt[b][n][c] ----------
__global__ void __launch_bounds__(256) transpose_kernel(const float* __restrict__ x) {
    __shared__ float t[64][65];
    const int b = blockIdx.y, n0 = blockIdx.x * 64;
    const int tid = threadIdx.x;
    const int nn = tid & 63, cq = tid >> 6;
#pragma unroll
    for (int i = 0; i < 16; ++i) {
        int c = i * 4 + cq;
        t[c][nn] = x[((size_t)b * CINCH + c) * NPTS + n0 + nn];
    }
    __syncthreads();
    const int nr = tid >> 2, q = tid & 3;
    float4* dst = (float4*)(g_xt + ((size_t)b * NPTS + n0 + nr) * CINCH);
#pragma unroll
    for (int i = 0; i < 4; ++i) {
        int c4 = i * 4 + q;
        dst[c4] = make_float4(t[c4 * 4 + 0][nr], t[c4 * 4 + 1][nr],
                              t[c4 * 4 + 2][nr], t[c4 * 4 + 3][nr]);
    }
}

// ---------- kernel 1: KNN (top-16 ascending d2, tie -> smaller index) + local coords ----
__global__ void __launch_bounds__(256) knn_kernel(const float* __restrict__ coords,
                                                  float* __restrict__ dout) {
    const int bn = blockIdx.x;
    const int b = bn >> 11, n = bn & (NPTS - 1);
    const int tid = threadIdx.x;
    const int w = tid >> 5, lane = tid & 31;
    const float* cb = coords + (size_t)b * 3 * NPTS;
    const float qx = cb[n], qy = cb[NPTS + n], qz = cb[2 * NPTS + n];
    const float sqn = __fadd_rn(__fadd_rn(__fmul_rn(qx, qx), __fmul_rn(qy, qy)),
                                __fmul_rn(qz, qz));

    unsigned long long keys[8];
#pragma unroll
    for (int i = 0; i < 8; ++i) {
        int m = tid + (i << 8);
        float mx = cb[m], my = cb[NPTS + m], mz = cb[2 * NPTS + m];
        float sqm = __fadd_rn(__fadd_rn(__fmul_rn(mx, mx), __fmul_rn(my, my)),
                              __fmul_rn(mz, mz));
        float dot = fmaf(qz, mz, fmaf(qy, my, __fmul_rn(qx, mx)));
        float t  = __fadd_rn(sqn, sqm);
        float d2 = __fsub_rn(t, __fmul_rn(2.0f, dot));
        unsigned u = __float_as_uint(d2);
        u = (u & 0x80000000u) ? ~u : (u | 0x80000000u);
        keys[i] = ((unsigned long long)u << 32) | (unsigned)m;
    }

    unsigned long long tmin =
        umin64(umin64(umin64(keys[0], keys[1]), umin64(keys[2], keys[3])),
               umin64(umin64(keys[4], keys[5]), umin64(keys[6], keys[7])));

    __shared__ unsigned long long wmin[8];
    __shared__ unsigned long long wsel[KNNK];

    for (int r = 0; r < KNNK; ++r) {
        unsigned long long v = tmin;
#pragma unroll
        for (int off = 16; off; off >>= 1)
            v = umin64(v, __shfl_xor_sync(0xffffffffu, v, off));
        if (lane == 0) wmin[w] = v;
        __syncthreads();
        if (tid == 0) {
            unsigned long long bb = wmin[0];
#pragma unroll
            for (int wi = 1; wi < 8; ++wi) bb = umin64(bb, wmin[wi]);
            wsel[r] = bb;
        }
        __syncthreads();
        unsigned long long kk = wsel[r];
        if (tmin == kk) {
#pragma unroll
            for (int i = 0; i < 8; ++i)
                keys[i] = (keys[i] == kk) ? ~0ull : keys[i];
            tmin = umin64(umin64(umin64(keys[0], keys[1]), umin64(keys[2], keys[3])),
                          umin64(umin64(keys[4], keys[5]), umin64(keys[6], keys[7])));
        }
    }

    if (tid < KNNK) g_idx[bn * KNNK + tid] = (int)(wsel[tid] & 0xffffffffull);
    if (tid < 3 * KNNK) {
        int c = tid >> 4, k = tid & 15;
        int id = (int)(wsel[k] & 0xffffffffull);
        float center = cb[c * NPTS + n];
        float nb = cb[c * NPTS + id];
        dout[LC_OFF + (((size_t)(b * 3 + c) * NPTS) + n) * KNNK + k] = __fsub_rn(center, nb);
    }
}

// ---------- kernel 2: persistent mma.sync 3xFP16-split MLP ----------
// 152 CTAs x 512 thr (16 warps). Tile = 8 points = 128 cols.
// Warp w: rows 16*(w&7)..+15, cols 64*(w>>3)..+63.
// SMEM (u32): W1 hi/lo [o128][cp32]@36, W2 hi/lo [o128][cp64]@68,
//             HS hi/lo col-major [col128][op64]@68 (X hi/lo [cp32][col128]@136 overlays HS).
#define W1S 36
#define W2S 68
#define HSS 68
#define XS  136
__global__ void __launch_bounds__(512, 1) mlp_mma_kernel(
    const float* __restrict__ w1, const float* __restrict__ w2,
    const float* __restrict__ g1, const float* __restrict__ b1,
    const float* __restrict__ m1, const float* __restrict__ v1,
    const float* __restrict__ g2, const float* __restrict__ b2,
    const float* __restrict__ m2, const float* __restrict__ v2,
    float* __restrict__ dout) {
    extern __shared__ uint32_t sm[];
    uint32_t* W1HI = sm;                  // 4608
    uint32_t* W1LO = sm + 4608;           // 4608
    uint32_t* W2HI = sm + 9216;           // 8704
    uint32_t* W2LO = sm + 17920;          // 8704
    uint32_t* HSHI = sm + 26624;          // 8704 (X-hi overlays first 4352)
    uint32_t* HSLO = sm + 35328;          // 8704 -> total 44032 u32 = 176128 B

    const int tid = threadIdx.x;
    const int w = tid >> 5, lane = tid & 31;
    const int gid = lane >> 2, tig = lane & 3;
    const int rowW = w & 7, colHalf = w >> 3;
    const int rA = rowW * 16 + gid, rB = rA + 8;

    // ---- prologue (once): W1, W2 -> SMEM fp16 hi/lo, half2-packed along c ----
    {
        const int o = tid >> 2, q = tid & 3;
#pragma unroll
        for (int i = 0; i < 4; ++i) {           // W1: 16 cols per thread
            float4 v = *(const float4*)(w1 + o * CINCH + q * 16 + i * 4);
            int cp = q * 8 + 2 * i;
            uint32_t h, l;
            h2split(v.x, v.y, h, l); W1HI[o * W1S + cp] = h;     W1LO[o * W1S + cp] = l;
            h2split(v.z, v.w, h, l); W1HI[o * W1S + cp + 1] = h; W1LO[o * W1S + cp + 1] = l;
        }
#pragma unroll
        for (int i = 0; i < 8; ++i) {           // W2: 32 cols per thread
            float4 v = *(const float4*)(w2 + o * COUTC + q * 32 + i * 4);
            int cp = q * 16 + 2 * i;
            uint32_t h, l;
            h2split(v.x, v.y, h, l); W2HI[o * W2S + cp] = h;     W2LO[o * W2S + cp] = l;
            h2split(v.z, v.w, h, l); W2HI[o * W2S + cp + 1] = h; W2LO[o * W2S + cp + 1] = l;
        }
    }

    // BN constants for rows rA, rB
    const float s1A = g1[rA] / sqrtf(v1[rA] + 1e-5f);
    const float c1A = b1[rA] - m1[rA] * s1A;
    const float s1B = g1[rB] / sqrtf(v1[rB] + 1e-5f);
    const float c1B = b1[rB] - m1[rB] * s1B;
    const float s2A = g2[rA] / sqrtf(v2[rA] + 1e-5f);
    const float c2A = b2[rA] - m2[rA] * s2A;
    const float s2B = g2[rB] / sqrtf(v2[rB] + 1e-5f);
    const float c2B = b2[rB] - m2[rB] * s2B;

    __half* HSHIh = (__half*)HSHI;   // half index = col*136 + o
    __half* HSLOh = (__half*)HSLO;

    for (int tile = blockIdx.x; tile < NTILES; tile += gridDim.x) {
        const int bIdx = tile >> 8;             // 256 tiles per batch
        const int np0  = (tile & 255) * 8;      // first point in batch

        // ---- gather + fp16 split: X[cp][col] (overlays HS) ----
        {
            const int col = tid & 127, q = tid >> 7;   // q: 16 channels each
            const int id = __ldg(&g_idx[tile * 128 + col]);
            const float4* src =
                (const float4*)(g_xt + ((size_t)bIdx * NPTS + id) * CINCH) + q * 4;
#pragma unroll
            for (int i = 0; i < 4; ++i) {
                float4 v = __ldg(&src[i]);
                int cp = q * 8 + 2 * i;
                uint32_t h, l;
                h2split(v.x, v.y, h, l);
                HSHI[cp * XS + col] = h; HSLO[cp * XS + col] = l;
                h2split(v.z, v.w, h, l);
                HSHI[(cp + 1) * XS + col] = h; HSLO[(cp + 1) * XS + col] = l;
            }
        }
        __syncthreads();

        float acc[8][4];
#pragma unroll
        for (int nt = 0; nt < 8; ++nt)
#pragma unroll
            for (int j = 0; j < 4; ++j) acc[nt][j] = 0.f;

        // ---- GEMM1: K=64 -> 4 k16-steps ----
#pragma unroll
        for (int s = 0; s < 4; ++s) {
            const int kp0 = s * 8;
            uint32_t A0h = W1HI[rA * W1S + kp0 + tig];
            uint32_t A1h = W1HI[rB * W1S + kp0 + tig];
            uint32_t A2h = W1HI[rA * W1S + kp0 + tig + 4];
            uint32_t A3h = W1HI[rB * W1S + kp0 + tig + 4];
            uint32_t A0l = W1LO[rA * W1S + kp0 + tig];
            uint32_t A1l = W1LO[rB * W1S + kp0 + tig];
            uint32_t A2l = W1LO[rA * W1S + kp0 + tig + 4];
            uint32_t A3l = W1LO[rB * W1S + kp0 + tig + 4];
#pragma unroll
            for (int nt = 0; nt < 8; ++nt) {
                const int col = colHalf * 64 + nt * 8 + gid;
                uint32_t B0h = HSHI[(kp0 + tig) * XS + col];
                uint32_t B1h = HSHI[(kp0 + tig + 4) * XS + col];
                uint32_t B0l = HSLO[(kp0 + tig) * XS + col];
                uint32_t B1l = HSLO[(kp0 + tig + 4) * XS + col];
                MMA_F16(acc[nt], A0h, A1h, A2h, A3h, B0h, B1h);
                MMA_F16(acc[nt], A0h, A1h, A2h, A3h, B0l, B1l);
                MMA_F16(acc[nt], A0l, A1l, A2l, A3l, B0h, B1h);
            }
        }
        __syncthreads();   // X fully consumed; HS region may now be overwritten

        // ---- epilogue 1: BN+ReLU -> HS (fp16 hi/lo, col-major) ----
#pragma unroll
        for (int nt = 0; nt < 8; ++nt) {
            const int colp = colHalf * 64 + nt * 8 + 2 * tig;
            float h0 = fmaxf(fmaf(acc[nt][0], s1A, c1A), 0.f);
            float h1 = fmaxf(fmaf(acc[nt][1], s1A, c1A), 0.f);
            float h2 = fmaxf(fmaf(acc[nt][2], s1B, c1B), 0.f);
            float h3 = fmaxf(fmaf(acc[nt][3], s1B, c1B), 0.f);
            __half hh, hl;
            hsplit(h0, hh, hl); HSHIh[colp * 136 + rA] = hh;       HSLOh[colp * 136 + rA] = hl;
            hsplit(h1, hh, hl); HSHIh[(colp + 1) * 136 + rA] = hh; HSLOh[(colp + 1) * 136 + rA] = hl;
            hsplit(h2, hh, hl); HSHIh[colp * 136 + rB] = hh;       HSLOh[colp * 136 + rB] = hl;
            hsplit(h3, hh, hl); HSHIh[(colp + 1) * 136 + rB] = hh; HSLOh[(colp + 1) * 136 + rB] = hl;
        }
        __syncthreads();

#pragma unroll
        for (int nt = 0; nt < 8; ++nt)
#pragma unroll
            for (int j = 0; j < 4; ++j) acc[nt][j] = 0.f;

        // ---- GEMM2: K=128 -> 8 k16-steps ----
#pragma unroll
        for (int s = 0; s < 8; ++s) {
            const int kp0 = s * 8;
            uint32_t A0h = W2HI[rA * W2S + kp0 + tig];
            uint32_t A1h = W2HI[rB * W2S + kp0 + tig];
            uint32_t A2h = W2HI[rA * W2S + kp0 + tig + 4];
            uint32_t A3h = W2HI[rB * W2S + kp0 + tig + 4];
            uint32_t A0l = W2LO[rA * W2S + kp0 + tig];
            uint32_t A1l = W2LO[rB * W2S + kp0 + tig];
            uint32_t A2l = W2LO[rA * W2S + kp0 + tig + 4];
            uint32_t A3l = W2LO[rB * W2S + kp0 + tig + 4];
#pragma unroll
            for (int nt = 0; nt < 8; ++nt) {
                const int col = colHalf * 64 + nt * 8 + gid;
                uint32_t B0h = HSHI[col * HSS + kp0 + tig];
                uint32_t B1h = HSHI[col * HSS + kp0 + tig + 4];
                uint32_t B0l = HSLO[col * HSS + kp0 + tig];
                uint32_t B1l = HSLO[col * HSS + kp0 + tig + 4];
                MMA_F16(acc[nt], A0h, A1h, A2h, A3h, B0h, B1h);
                MMA_F16(acc[nt], A0h, A1h, A2h, A3h, B0l, B1l);
                MMA_F16(acc[nt], A0l, A1l, A2l, A3l, B0h, B1h);
            }
        }

        // ---- epilogue 2: BN+ReLU, write knn_mlp_x + y ----
        {
            float* out2 = dout + OUT2_OFF;
            float pmA[4], pmB[4];
#pragma unroll
            for (int pp = 0; pp < 4; ++pp) { pmA[pp] = 0.f; pmB[pp] = 0.f; }
#pragma unroll
            for (int nt = 0; nt < 8; ++nt) {
                float v0 = fmaxf(fmaf(acc[nt][0], s2A, c2A), 0.f);
                float v1 = fmaxf(fmaf(acc[nt][1], s2A, c2A), 0.f);
                float v2_ = fmaxf(fmaf(acc[nt][2], s2B, c2B), 0.f);
                float v3 = fmaxf(fmaf(acc[nt][3], s2B, c2B), 0.f);
                const int pp = nt >> 1;
                const int kk = (nt & 1) * 8 + 2 * tig;
                pmA[pp] = fmaxf(pmA[pp], fmaxf(v0, v1));
                pmB[pp] = fmaxf(pmB[pp], fmaxf(v2_, v3));
                const int n = np0 + colHalf * 4 + pp;
                float* pA = out2 + (((size_t)(bIdx * COUTC + rA)) * NPTS + n) * KNNK + kk;
                float* pB = out2 + (((size_t)(bIdx * COUTC + rB)) * NPTS + n) * KNNK + kk;
                *(float2*)pA = make_float2(v0, v1);
                *(float2*)pB = make_float2(v2_, v3);
            }
#pragma unroll
            for (int pp = 0; pp < 4; ++pp) {
                float mA = pmA[pp], mB = pmB[pp];
                mA = fmaxf(mA, __shfl_xor_sync(0xffffffffu, mA, 1));
                mA = fmaxf(mA, __shfl_xor_sync(0xffffffffu, mA, 2));
                mB = fmaxf(mB, __shfl_xor_sync(0xffffffffu, mB, 1));
                mB = fmaxf(mB, __shfl_xor_sync(0xffffffffu, mB, 2));
                if (tig == 0) {
                    const int n = np0 + colHalf * 4 + pp;
                    dout[(size_t)(bIdx * COUTC + rA) * NPTS + n] = mA;
                    dout[(size_t)(bIdx * COUTC + rB) * NPTS + n] = mB;
                }
            }
        }
        __syncthreads();   // protect HS before next tile's gather overwrites it
    }
}

extern "C" void kernel_launch(void* const* d_in, const int* in_sizes, int n_in,
                              void* d_out, int out_size) {
    const float* x      = (const float*)d_in[0];
    const float* coords = (const float*)d_in[1];
    const float* w1     = (const float*)d_in[2];
    const float* g1     = (const float*)d_in[3];
    const float* b1     = (const float*)d_in[4];
    const float* m1     = (const float*)d_in[5];
    const float* v1     = (const float*)d_in[6];
    const float* w2     = (const float*)d_in[7];
    const float* g2     = (const float*)d_in[8];
    const float* b2     = (const float*)d_in[9];
    const float* m2     = (const float*)d_in[10];
    const float* v2     = (const float*)d_in[11];
    float* out = (float*)d_out;

    transpose_kernel<<<dim3(NPTS / 64, BATCH), 256>>>(x);
    knn_kernel<<<BATCH * NPTS, 256>>>(coords, out);

    const int smem_bytes = 44032 * 4;   // 176,128 B
    cudaFuncSetAttribute(mlp_mma_kernel, cudaFuncAttributeMaxDynamicSharedMemorySize, smem_bytes);
    mlp_mma_kernel<<<152, 512, smem_bytes>>>(
        w1, w2, g1, b1, m1, v1, g2, b2, m2, v2, out);
}